// round 11
// baseline (speedup 1.0000x reference)
#include <cuda_runtime.h>
#include <cuda_bf16.h>

#define N_BITS   128
#define NEURONS  512
#define BT       8      // batches per thread
#define TPB      128    // threads per block = neurons per block
#define CHUNK    16     // factors per partial product

typedef unsigned long long u64;

__device__ __forceinline__ u64 pk2(float lo, float hi) {
    u64 r; asm("mov.b64 %0, {%1, %2};" : "=l"(r) : "f"(lo), "f"(hi)); return r;
}
__device__ __forceinline__ void upk2(float& lo, float& hi, u64 p) {
    asm("mov.b64 {%0, %1}, %2;" : "=f"(lo), "=f"(hi) : "l"(p));
}
__device__ __forceinline__ u64 mul2(u64 a, u64 b) {
    u64 r; asm("mul.rn.f32x2 %0, %1, %2;" : "=l"(r) : "l"(a), "l"(b)); return r;
}
__device__ __forceinline__ u64 fma2(u64 a, u64 b, u64 c) {
    u64 r; asm("fma.rn.f32x2 %0, %1, %2, %3;" : "=l"(r) : "l"(a), "l"(b), "l"(c)); return r;
}

// [4/5] Pade for u = tanh(v/2), sigma = v^2:
//   num = v*(0.5 + A1*sigma + A2*sigma^2);  den = 1 + D1*sigma + D2*sigma^2
#define A1C  0.013888888888888888f
#define A2C  3.306878306878307e-5f
#define D1C  0.1111111111111111f
#define D2C  9.920634920634921e-4f
// exp(-1e6|u|) zone: E/|u| > 1e-4 only for |u| < ~2.1e-5 -> |v| < 4.2e-5.
// TH_T = 4.5e-5 (margin). Outside it the E term shifts a factor by <1.3e-5 rel.
#define TH_T 4.5e-5f
#define TH2  2.025e-9f               // TH_T^2

__global__ __launch_bounds__(TPB) void bp_input_layer_kernel(
    const float* __restrict__ x,      // [B, 128]
    const float* __restrict__ W,      // [128, 512]
    float* __restrict__ out)          // [B, 512]
{
    __shared__ __align__(16) float xs[N_BITS * BT];  // xs[i*8+k] = x[b0+k][i]
    __shared__ float xmin[N_BITS];                   // min_k |x[b0+k][i]|

    const int tid = threadIdx.x;
    const int n   = blockIdx.x * TPB + tid;          // neuron index
    const int b0  = blockIdx.y * BT;

    // Stage x (thread t owns bit-column t, coalesced across threads) + xmin
    {
        float mn = 1e30f;
#pragma unroll
        for (int k = 0; k < BT; ++k) {
            float v = x[(b0 + k) * N_BITS + tid];
            xs[tid * BT + k] = v;
            mn = fminf(mn, fabsf(v));
        }
        xmin[tid] = mn;
    }
    __syncthreads();

    const u64 ONEP = pk2(1.0f, 1.0f), HLFP = pk2(0.5f, 0.5f);
    const u64 A1P = pk2(A1C, A1C), A2P = pk2(A2C, A2C);
    const u64 D1P = pk2(D1C, D1C), D2P = pk2(D2C, D2C);

    float z[BT];
#pragma unroll
    for (int k = 0; k < BT; ++k) z[k] = 1.0f;

    const float* Wp = W + n;

    for (int c = 0; c < N_BITS / CHUNK; ++c) {
        u64 npA = ONEP, npB = ONEP, npC = ONEP, npD = ONEP;
        u64 dpA = ONEP, dpB = ONEP, dpC = ONEP, dpD = ONEP;
#pragma unroll
        for (int j = 0; j < CHUNK; ++j) {
            const int i = c * CHUNK + j;
            const float w   = Wp[i * NEURONS];           // coalesced LDG, L2-hot
            const float xmv = xmin[i];                   // LDS broadcast
            const u64 ww = pk2(w, w);
            const ulonglong2* xp = reinterpret_cast<const ulonglong2*>(&xs[i * BT]);
            const ulonglong2 q0 = xp[0], q1 = xp[1];     // 2x LDS.128 broadcast

            u64 vA = mul2(q0.x, ww), vB = mul2(q0.y, ww);
            u64 vC = mul2(q1.x, ww), vD = mul2(q1.y, ww);

            u64 sA = mul2(vA, vA), sB = mul2(vB, vB);    // sigma = v^2
            u64 sC = mul2(vC, vC), sD = mul2(vD, vD);

            // numerator: v * (0.5 + A1 s + A2 s^2)
            u64 pA = fma2(sA, A2P, A1P), pB = fma2(sB, A2P, A1P);
            u64 pC = fma2(sC, A2P, A1P), pD = fma2(sD, A2P, A1P);
            pA = fma2(sA, pA, HLFP); pB = fma2(sB, pB, HLFP);
            pC = fma2(sC, pC, HLFP); pD = fma2(sD, pD, HLFP);
            u64 nmA = mul2(vA, pA), nmB = mul2(vB, pB);
            u64 nmC = mul2(vC, pC), nmD = mul2(vD, pD);

            // denominator: 1 + D1 s + D2 s^2
            u64 qA = fma2(sA, D2P, D1P), qB = fma2(sB, D2P, D1P);
            u64 qC = fma2(sC, D2P, D1P), qD = fma2(sD, D2P, D1P);
            qA = fma2(sA, qA, ONEP); qB = fma2(sB, qB, ONEP);
            qC = fma2(sC, qC, ONEP); qD = fma2(sD, qD, ONEP);

            // exp(-1e6|u|) zone: min_k |v_k| = |w|*xmin[i] exactly.
            // One scalar compare + vote; fires ~9% of (warp,j) now.
            if (__any_sync(0xffffffffu, fabsf(w) * xmv < TH_T)) {
                float v0,v1,v2,v3,v4,v5,v6,v7;
                float s0,s1,s2,s3,s4,s5,s6,s7;
                float n0,n1,n2,n3,n4,n5,n6,n7;
                float d0,d1,d2,d3,d4,d5,d6,d7;
                upk2(v0, v1, vA); upk2(v2, v3, vB);
                upk2(v4, v5, vC); upk2(v6, v7, vD);
                upk2(s0, s1, sA); upk2(s2, s3, sB);
                upk2(s4, s5, sC); upk2(s6, s7, sD);
                upk2(n0, n1, nmA); upk2(n2, n3, nmB);
                upk2(n4, n5, nmC); upk2(n6, n7, nmD);
                upk2(d0, d1, qA); upk2(d2, d3, qB);
                upk2(d4, d5, qC); upk2(d6, d7, qD);
                // num' = num + den*E, E = exp(-1e6|u|), u ~ v/2 (v==0 -> factor 1)
                if (s0 < TH2) n0 = fmaf(__expf(-5e5f*fabsf(v0)), d0, n0);
                if (s1 < TH2) n1 = fmaf(__expf(-5e5f*fabsf(v1)), d1, n1);
                if (s2 < TH2) n2 = fmaf(__expf(-5e5f*fabsf(v2)), d2, n2);
                if (s3 < TH2) n3 = fmaf(__expf(-5e5f*fabsf(v3)), d3, n3);
                if (s4 < TH2) n4 = fmaf(__expf(-5e5f*fabsf(v4)), d4, n4);
                if (s5 < TH2) n5 = fmaf(__expf(-5e5f*fabsf(v5)), d5, n5);
                if (s6 < TH2) n6 = fmaf(__expf(-5e5f*fabsf(v6)), d6, n6);
                if (s7 < TH2) n7 = fmaf(__expf(-5e5f*fabsf(v7)), d7, n7);
                nmA = pk2(n0, n1); nmB = pk2(n2, n3);
                nmC = pk2(n4, n5); nmD = pk2(n6, n7);
            }

            npA = mul2(npA, nmA); npB = mul2(npB, nmB);
            npC = mul2(npC, nmC); npD = mul2(npD, nmD);
            dpA = mul2(dpA, qA);  dpB = mul2(dpB, qB);
            dpC = mul2(dpC, qC);  dpD = mul2(dpD, qD);
        }
        float f0,f1,f2,f3,f4,f5,f6,f7, g0,g1,g2,g3,g4,g5,g6,g7;
        upk2(f0, f1, npA); upk2(f2, f3, npB);
        upk2(f4, f5, npC); upk2(f6, f7, npD);
        upk2(g0, g1, dpA); upk2(g2, g3, dpB);
        upk2(g4, g5, dpC); upk2(g6, g7, dpD);
        z[0] *= __fdividef(f0, g0); z[1] *= __fdividef(f1, g1);
        z[2] *= __fdividef(f2, g2); z[3] *= __fdividef(f3, g3);
        z[4] *= __fdividef(f4, g4); z[5] *= __fdividef(f5, g5);
        z[6] *= __fdividef(f6, g6); z[7] *= __fdividef(f7, g7);
    }

#pragma unroll
    for (int k = 0; k < BT; ++k) {
        float a = (1.0f + z[k]) + 1e-8f;
        float b = (1.0f - z[k]) + 1e-8f;
        out[(b0 + k) * NEURONS + n] = __logf(a / b);
    }
}

extern "C" void kernel_launch(void* const* d_in, const int* in_sizes, int n_in,
                              void* d_out, int out_size)
{
    const float* x = (const float*)d_in[0];   // [B, 128] float32
    const float* W = (const float*)d_in[1];   // [128, 512] float32
    float* out = (float*)d_out;               // [B, 512] float32

    const int B = in_sizes[0] / N_BITS;       // 2048
    dim3 grid(NEURONS / TPB, B / BT);         // (4, 256) -> 1024 blocks
    bp_input_layer_kernel<<<grid, TPB>>>(x, W, out);
}

// round 12
// speedup vs baseline: 1.0058x; 1.0058x over previous
#include <cuda_runtime.h>
#include <cuda_bf16.h>

#define N_BITS   128
#define NEURONS  512
#define BT       4      // batches per thread
#define TPB      128    // threads per block = neurons per block
#define CHUNK    16     // factors per partial product

typedef unsigned long long u64;

__device__ __forceinline__ u64 pk2(float lo, float hi) {
    u64 r; asm("mov.b64 %0, {%1, %2};" : "=l"(r) : "f"(lo), "f"(hi)); return r;
}
__device__ __forceinline__ void upk2(float& lo, float& hi, u64 p) {
    asm("mov.b64 {%0, %1}, %2;" : "=f"(lo), "=f"(hi) : "l"(p));
}
__device__ __forceinline__ u64 mul2(u64 a, u64 b) {
    u64 r; asm("mul.rn.f32x2 %0, %1, %2;" : "=l"(r) : "l"(a), "l"(b)); return r;
}
__device__ __forceinline__ u64 fma2(u64 a, u64 b, u64 c) {
    u64 r; asm("fma.rn.f32x2 %0, %1, %2, %3;" : "=l"(r) : "l"(a), "l"(b), "l"(c)); return r;
}

// [4/5] Pade for u = tanh(v/2), sigma = v^2:
//   num = v*(0.5 + A1*sigma + A2*sigma^2);  den = 1 + D1*sigma + D2*sigma^2
#define A1C  0.013888888888888888f
#define A2C  3.306878306878307e-5f
#define D1C  0.1111111111111111f
#define D2C  9.920634920634921e-4f
// exp(-1e6|u|) zone: E/|u| > 1e-4 only for |u| < ~2.1e-5 -> |v| < 4.2e-5.
#define TH_T 4.5e-5f
#define TH2  2.025e-9f               // TH_T^2

__global__ __launch_bounds__(TPB, 10) void bp_input_layer_kernel(
    const float* __restrict__ x,      // [B, 128]
    const float* __restrict__ W,      // [128, 512]
    float* __restrict__ out)          // [B, 512]
{
    __shared__ __align__(16) float xs[N_BITS * BT];  // xs[i*4+k] = x[b0+k][i]
    __shared__ float xmin[N_BITS];                   // min_k |x[b0+k][i]|

    const int tid = threadIdx.x;
    const int n   = blockIdx.x * TPB + tid;          // neuron index
    const int b0  = blockIdx.y * BT;

    // Stage x (thread t owns bit-column t, coalesced across threads) + xmin
    {
        float mn = 1e30f;
#pragma unroll
        for (int k = 0; k < BT; ++k) {
            float v = x[(b0 + k) * N_BITS + tid];
            xs[tid * BT + k] = v;
            mn = fminf(mn, fabsf(v));
        }
        xmin[tid] = mn;
    }
    __syncthreads();

    const u64 ONEP = pk2(1.0f, 1.0f), HLFP = pk2(0.5f, 0.5f);
    const u64 A1P = pk2(A1C, A1C), A2P = pk2(A2C, A2C);
    const u64 D1P = pk2(D1C, D1C), D2P = pk2(D2C, D2C);

    float z[BT];
#pragma unroll
    for (int k = 0; k < BT; ++k) z[k] = 1.0f;

    const float* Wp = W + n;

    for (int c = 0; c < N_BITS / CHUNK; ++c) {
        u64 npA = ONEP, npB = ONEP;
        u64 dpA = ONEP, dpB = ONEP;
#pragma unroll
        for (int j = 0; j < CHUNK; ++j) {
            const int i = c * CHUNK + j;
            const float w   = Wp[i * NEURONS];           // coalesced LDG, L2-hot
            const float xmv = xmin[i];                   // LDS broadcast
            const u64 ww = pk2(w, w);
            const ulonglong2 q0 =
                *reinterpret_cast<const ulonglong2*>(&xs[i * BT]); // LDS.128

            u64 vA = mul2(q0.x, ww), vB = mul2(q0.y, ww);
            u64 sA = mul2(vA, vA),   sB = mul2(vB, vB);  // sigma = v^2

            // numerator: v * (0.5 + A1 s + A2 s^2)
            u64 pA = fma2(sA, A2P, A1P), pB = fma2(sB, A2P, A1P);
            pA = fma2(sA, pA, HLFP); pB = fma2(sB, pB, HLFP);
            u64 nmA = mul2(vA, pA), nmB = mul2(vB, pB);

            // denominator: 1 + D1 s + D2 s^2
            u64 qA = fma2(sA, D2P, D1P), qB = fma2(sB, D2P, D1P);
            qA = fma2(sA, qA, ONEP); qB = fma2(sB, qB, ONEP);

            // exp(-1e6|u|) zone: min_k |v_k| = |w|*xmin[i] exactly; rare vote.
            if (__any_sync(0xffffffffu, fabsf(w) * xmv < TH_T)) {
                float v0,v1,v2,v3, s0,s1,s2,s3;
                float n0,n1,n2,n3, d0,d1,d2,d3;
                upk2(v0, v1, vA); upk2(v2, v3, vB);
                upk2(s0, s1, sA); upk2(s2, s3, sB);
                upk2(n0, n1, nmA); upk2(n2, n3, nmB);
                upk2(d0, d1, qA); upk2(d2, d3, qB);
                // num' = num + den*E, E = exp(-1e6|u|), u ~ v/2 (v==0 -> factor 1)
                if (s0 < TH2) n0 = fmaf(__expf(-5e5f*fabsf(v0)), d0, n0);
                if (s1 < TH2) n1 = fmaf(__expf(-5e5f*fabsf(v1)), d1, n1);
                if (s2 < TH2) n2 = fmaf(__expf(-5e5f*fabsf(v2)), d2, n2);
                if (s3 < TH2) n3 = fmaf(__expf(-5e5f*fabsf(v3)), d3, n3);
                nmA = pk2(n0, n1); nmB = pk2(n2, n3);
            }

            npA = mul2(npA, nmA); npB = mul2(npB, nmB);
            dpA = mul2(dpA, qA);  dpB = mul2(dpB, qB);
        }
        float f0,f1,f2,f3, g0,g1,g2,g3;
        upk2(f0, f1, npA); upk2(f2, f3, npB);
        upk2(g0, g1, dpA); upk2(g2, g3, dpB);
        z[0] *= __fdividef(f0, g0); z[1] *= __fdividef(f1, g1);
        z[2] *= __fdividef(f2, g2); z[3] *= __fdividef(f3, g3);
    }

#pragma unroll
    for (int k = 0; k < BT; ++k) {
        float a = (1.0f + z[k]) + 1e-8f;
        float b = (1.0f - z[k]) + 1e-8f;
        out[(b0 + k) * NEURONS + n] = __logf(a / b);
    }
}

extern "C" void kernel_launch(void* const* d_in, const int* in_sizes, int n_in,
                              void* d_out, int out_size)
{
    const float* x = (const float*)d_in[0];   // [B, 128] float32
    const float* W = (const float*)d_in[1];   // [128, 512] float32
    float* out = (float*)d_out;               // [B, 512] float32

    const int B = in_sizes[0] / N_BITS;       // 2048
    dim3 grid(NEURONS / TPB, B / BT);         // (4, 512) -> 2048 blocks
    bp_input_layer_kernel<<<grid, TPB>>>(x, W, out);
}

// round 13
// speedup vs baseline: 1.8002x; 1.7899x over previous
#include <cuda_runtime.h>
#include <cuda_bf16.h>

#define N_BITS   128
#define NEURONS  512
#define BT       8      // batches per thread
#define TPB      128    // threads per block = neurons per block
#define CHUNK    16     // factors per partial product

typedef unsigned long long u64;

__device__ __forceinline__ u64 pk2(float lo, float hi) {
    u64 r; asm("mov.b64 %0, {%1, %2};" : "=l"(r) : "f"(lo), "f"(hi)); return r;
}
__device__ __forceinline__ void upk2(float& lo, float& hi, u64 p) {
    asm("mov.b64 {%0, %1}, %2;" : "=f"(lo), "=f"(hi) : "l"(p));
}
__device__ __forceinline__ u64 mul2(u64 a, u64 b) {
    u64 r; asm("mul.rn.f32x2 %0, %1, %2;" : "=l"(r) : "l"(a), "l"(b)); return r;
}
__device__ __forceinline__ u64 fma2(u64 a, u64 b, u64 c) {
    u64 r; asm("fma.rn.f32x2 %0, %1, %2, %3;" : "=l"(r) : "l"(a), "l"(b), "l"(c)); return r;
}

// [4/5] Pade for u = tanh(v/2), sigma = v^2:
//   num = v*(0.5 + A1*sigma + A2*sigma^2);  den = 1 + D1*sigma + D2*sigma^2
#define A1C  0.013888888888888888f
#define A2C  3.306878306878307e-5f
#define D1C  0.1111111111111111f
#define D2C  9.920634920634921e-4f
// exp(-1e6|u|) zone: E/|u| > 1e-4 only for |u| < ~2.1e-5 -> |v| < 4.2e-5.
#define TH_T 4.5e-5f
#define TH2  2.025e-9f               // TH_T^2

__global__ __launch_bounds__(TPB) void bp_input_layer_kernel(
    const float* __restrict__ x,      // [B, 128]
    const float* __restrict__ W,      // [128, 512]
    float* __restrict__ out)          // [B, 512]
{
    __shared__ __align__(16) float xs[N_BITS * BT];  // xs[i*8+k] = x[b0+k][i]
    __shared__ float xmin[N_BITS];                   // min_k |x[b0+k][i]|

    const int tid = threadIdx.x;
    const int n   = blockIdx.x * TPB + tid;          // neuron index
    const int b0  = blockIdx.y * BT;

    // Stage x (thread t owns bit-column t, coalesced across threads) + xmin
    {
        float mn = 1e30f;
#pragma unroll
        for (int k = 0; k < BT; ++k) {
            float v = x[(b0 + k) * N_BITS + tid];
            xs[tid * BT + k] = v;
            mn = fminf(mn, fabsf(v));
        }
        xmin[tid] = mn;
    }
    __syncthreads();

    const u64 ONEP = pk2(1.0f, 1.0f), HLFP = pk2(0.5f, 0.5f);
    const u64 A1P = pk2(A1C, A1C), A2P = pk2(A2C, A2C);
    const u64 D1P = pk2(D1C, D1C), D2P = pk2(D2C, D2C);

    float z[BT];
#pragma unroll
    for (int k = 0; k < BT; ++k) z[k] = 1.0f;

    const float* Wp = W + n;

    for (int c = 0; c < N_BITS / CHUNK; ++c) {
        u64 npA = ONEP, npB = ONEP, npC = ONEP, npD = ONEP;
        u64 dpA = ONEP, dpB = ONEP, dpC = ONEP, dpD = ONEP;
#pragma unroll
        for (int j = 0; j < CHUNK; ++j) {
            const int i = c * CHUNK + j;
            const float w   = Wp[i * NEURONS];           // coalesced LDG, L2-hot
            const float xmv = xmin[i];                   // LDS broadcast
            const u64 ww = pk2(w, w);
            const ulonglong2* xp = reinterpret_cast<const ulonglong2*>(&xs[i * BT]);
            const ulonglong2 q0 = xp[0], q1 = xp[1];     // 2x LDS.128 broadcast

            u64 vA = mul2(q0.x, ww), vB = mul2(q0.y, ww);
            u64 vC = mul2(q1.x, ww), vD = mul2(q1.y, ww);

            u64 sA = mul2(vA, vA), sB = mul2(vB, vB);    // sigma = v^2
            u64 sC = mul2(vC, vC), sD = mul2(vD, vD);

            // numerator: v * (0.5 + A1 s + A2 s^2)
            u64 pA = fma2(sA, A2P, A1P), pB = fma2(sB, A2P, A1P);
            u64 pC = fma2(sC, A2P, A1P), pD = fma2(sD, A2P, A1P);
            pA = fma2(sA, pA, HLFP); pB = fma2(sB, pB, HLFP);
            pC = fma2(sC, pC, HLFP); pD = fma2(sD, pD, HLFP);
            u64 nmA = mul2(vA, pA), nmB = mul2(vB, pB);
            u64 nmC = mul2(vC, pC), nmD = mul2(vD, pD);

            // denominator: 1 + D1 s + D2 s^2
            u64 qA = fma2(sA, D2P, D1P), qB = fma2(sB, D2P, D1P);
            u64 qC = fma2(sC, D2P, D1P), qD = fma2(sD, D2P, D1P);
            qA = fma2(sA, qA, ONEP); qB = fma2(sB, qB, ONEP);
            qC = fma2(sC, qC, ONEP); qD = fma2(sD, qD, ONEP);

            // exp(-1e6|u|) zone: min_k |v_k| = |w|*xmin[i] exactly; rare vote.
            if (__any_sync(0xffffffffu, fabsf(w) * xmv < TH_T)) {
                float v0,v1,v2,v3,v4,v5,v6,v7;
                float s0,s1,s2,s3,s4,s5,s6,s7;
                float n0,n1,n2,n3,n4,n5,n6,n7;
                float d0,d1,d2,d3,d4,d5,d6,d7;
                upk2(v0, v1, vA); upk2(v2, v3, vB);
                upk2(v4, v5, vC); upk2(v6, v7, vD);
                upk2(s0, s1, sA); upk2(s2, s3, sB);
                upk2(s4, s5, sC); upk2(s6, s7, sD);
                upk2(n0, n1, nmA); upk2(n2, n3, nmB);
                upk2(n4, n5, nmC); upk2(n6, n7, nmD);
                upk2(d0, d1, qA); upk2(d2, d3, qB);
                upk2(d4, d5, qC); upk2(d6, d7, qD);
                // num' = num + den*E, E = exp(-1e6|u|), u ~ v/2 (v==0 -> factor 1)
                if (s0 < TH2) n0 = fmaf(__expf(-5e5f*fabsf(v0)), d0, n0);
                if (s1 < TH2) n1 = fmaf(__expf(-5e5f*fabsf(v1)), d1, n1);
                if (s2 < TH2) n2 = fmaf(__expf(-5e5f*fabsf(v2)), d2, n2);
                if (s3 < TH2) n3 = fmaf(__expf(-5e5f*fabsf(v3)), d3, n3);
                if (s4 < TH2) n4 = fmaf(__expf(-5e5f*fabsf(v4)), d4, n4);
                if (s5 < TH2) n5 = fmaf(__expf(-5e5f*fabsf(v5)), d5, n5);
                if (s6 < TH2) n6 = fmaf(__expf(-5e5f*fabsf(v6)), d6, n6);
                if (s7 < TH2) n7 = fmaf(__expf(-5e5f*fabsf(v7)), d7, n7);
                nmA = pk2(n0, n1); nmB = pk2(n2, n3);
                nmC = pk2(n4, n5); nmD = pk2(n6, n7);
            }

            npA = mul2(npA, nmA); npB = mul2(npB, nmB);
            npC = mul2(npC, nmC); npD = mul2(npD, nmD);
            dpA = mul2(dpA, qA);  dpB = mul2(dpB, qB);
            dpC = mul2(dpC, qC);  dpD = mul2(dpD, qD);
        }
        float f0,f1,f2,f3,f4,f5,f6,f7, g0,g1,g2,g3,g4,g5,g6,g7;
        upk2(f0, f1, npA); upk2(f2, f3, npB);
        upk2(f4, f5, npC); upk2(f6, f7, npD);
        upk2(g0, g1, dpA); upk2(g2, g3, dpB);
        upk2(g4, g5, dpC); upk2(g6, g7, dpD);
        z[0] *= __fdividef(f0, g0); z[1] *= __fdividef(f1, g1);
        z[2] *= __fdividef(f2, g2); z[3] *= __fdividef(f3, g3);
        z[4] *= __fdividef(f4, g4); z[5] *= __fdividef(f5, g5);
        z[6] *= __fdividef(f6, g6); z[7] *= __fdividef(f7, g7);

        // Early exit: z only shrinks (|factor| <= ~1); once ALL 256 z's in the
        // warp are exactly 0.0f, remaining chunks multiply 0 by finite factors
        // -> identity. Bitwise-exact skip. Integer |z| OR-tree runs on alu pipe.
        unsigned zo = (__float_as_uint(z[0]) | __float_as_uint(z[1]) |
                       __float_as_uint(z[2]) | __float_as_uint(z[3]) |
                       __float_as_uint(z[4]) | __float_as_uint(z[5]) |
                       __float_as_uint(z[6]) | __float_as_uint(z[7])) & 0x7fffffffu;
        if (__all_sync(0xffffffffu, zo == 0u)) break;
    }

#pragma unroll
    for (int k = 0; k < BT; ++k) {
        float a = (1.0f + z[k]) + 1e-8f;
        float b = (1.0f - z[k]) + 1e-8f;
        out[(b0 + k) * NEURONS + n] = __logf(a / b);
    }
}

extern "C" void kernel_launch(void* const* d_in, const int* in_sizes, int n_in,
                              void* d_out, int out_size)
{
    const float* x = (const float*)d_in[0];   // [B, 128] float32
    const float* W = (const float*)d_in[1];   // [128, 512] float32
    float* out = (float*)d_out;               // [B, 512] float32

    const int B = in_sizes[0] / N_BITS;       // 2048
    dim3 grid(NEURONS / TPB, B / BT);         // (4, 256) -> 1024 blocks
    bp_input_layer_kernel<<<grid, TPB>>>(x, W, out);
}

// round 15
// speedup vs baseline: 2.0952x; 1.1639x over previous
#include <cuda_runtime.h>
#include <cuda_bf16.h>

#define N_BITS   128
#define NEURONS  512
#define BT       8      // batches per thread
#define TPB      128    // threads per block = neurons per block
#define CHUNK    16     // factors per partial product

typedef unsigned long long u64;

__device__ __forceinline__ u64 pk2(float lo, float hi) {
    u64 r; asm("mov.b64 %0, {%1, %2};" : "=l"(r) : "f"(lo), "f"(hi)); return r;
}
__device__ __forceinline__ void upk2(float& lo, float& hi, u64 p) {
    asm("mov.b64 {%0, %1}, %2;" : "=f"(lo), "=f"(hi) : "l"(p));
}
__device__ __forceinline__ u64 mul2(u64 a, u64 b) {
    u64 r; asm("mul.rn.f32x2 %0, %1, %2;" : "=l"(r) : "l"(a), "l"(b)); return r;
}
__device__ __forceinline__ u64 fma2(u64 a, u64 b, u64 c) {
    u64 r; asm("fma.rn.f32x2 %0, %1, %2, %3;" : "=l"(r) : "l"(a), "l"(b), "l"(c)); return r;
}

// [4/5] Pade for u = tanh(v/2), sigma = v^2:
//   num = v*(0.5 + A1*sigma + A2*sigma^2);  den = 1 + D1*sigma + D2*sigma^2
#define A1C  0.013888888888888888f
#define A2C  3.306878306878307e-5f
#define D1C  0.1111111111111111f
#define D2C  9.920634920634921e-4f
// exp(-1e6|u|) zone: E/|u| > 1e-4 only for |u| < ~2.1e-5 -> |v| < 4.2e-5.
#define TH_T 4.5e-5f
#define TH2  2.025e-9f               // TH_T^2
// Early-exit threshold: once max|z| < ZCUT, the >=16 remaining factors
// (each |u+E| <= ~1, typically ~0.2) drive z (ours AND the f32 reference's)
// to exact 0. Exit with z := 0 reproduces the reference zeros exactly.
// Note f32 epilogue maps any |z| < ~5.9e-8 to output 0.0 anyway -> huge margin.
#define ZCUT 1e-30f

__global__ __launch_bounds__(TPB) void bp_input_layer_kernel(
    const float* __restrict__ x,      // [B, 128]
    const float* __restrict__ W,      // [128, 512]
    float* __restrict__ out)          // [B, 512]
{
    __shared__ __align__(16) float xs[N_BITS * BT];  // xs[i*8+k] = x[b0+k][i]
    __shared__ float xmin[N_BITS];                   // min_k |x[b0+k][i]|

    const int tid = threadIdx.x;
    const int n   = blockIdx.x * TPB + tid;          // neuron index
    const int b0  = blockIdx.y * BT;

    // Stage x (thread t owns bit-column t, coalesced across threads) + xmin
    {
        float mn = 1e30f;
#pragma unroll
        for (int k = 0; k < BT; ++k) {
            float v = x[(b0 + k) * N_BITS + tid];
            xs[tid * BT + k] = v;
            mn = fminf(mn, fabsf(v));
        }
        xmin[tid] = mn;
    }
    __syncthreads();

    const u64 ONEP = pk2(1.0f, 1.0f), HLFP = pk2(0.5f, 0.5f);
    const u64 A1P = pk2(A1C, A1C), A2P = pk2(A2C, A2C);
    const u64 D1P = pk2(D1C, D1C), D2P = pk2(D2C, D2C);

    float z[BT];
#pragma unroll
    for (int k = 0; k < BT; ++k) z[k] = 1.0f;

    const float* Wp = W + n;

    for (int c = 0; c < N_BITS / CHUNK; ++c) {
        u64 npA = ONEP, npB = ONEP, npC = ONEP, npD = ONEP;
        u64 dpA = ONEP, dpB = ONEP, dpC = ONEP, dpD = ONEP;
#pragma unroll
        for (int j = 0; j < CHUNK; ++j) {
            const int i = c * CHUNK + j;
            const float w   = Wp[i * NEURONS];           // coalesced LDG, L2-hot
            const float xmv = xmin[i];                   // LDS broadcast
            const u64 ww = pk2(w, w);
            const ulonglong2* xp = reinterpret_cast<const ulonglong2*>(&xs[i * BT]);
            const ulonglong2 q0 = xp[0], q1 = xp[1];     // 2x LDS.128 broadcast

            u64 vA = mul2(q0.x, ww), vB = mul2(q0.y, ww);
            u64 vC = mul2(q1.x, ww), vD = mul2(q1.y, ww);

            u64 sA = mul2(vA, vA), sB = mul2(vB, vB);    // sigma = v^2
            u64 sC = mul2(vC, vC), sD = mul2(vD, vD);

            // numerator: v * (0.5 + A1 s + A2 s^2)
            u64 pA = fma2(sA, A2P, A1P), pB = fma2(sB, A2P, A1P);
            u64 pC = fma2(sC, A2P, A1P), pD = fma2(sD, A2P, A1P);
            pA = fma2(sA, pA, HLFP); pB = fma2(sB, pB, HLFP);
            pC = fma2(sC, pC, HLFP); pD = fma2(sD, pD, HLFP);
            u64 nmA = mul2(vA, pA), nmB = mul2(vB, pB);
            u64 nmC = mul2(vC, pC), nmD = mul2(vD, pD);

            // denominator: 1 + D1 s + D2 s^2
            u64 qA = fma2(sA, D2P, D1P), qB = fma2(sB, D2P, D1P);
            u64 qC = fma2(sC, D2P, D1P), qD = fma2(sD, D2P, D1P);
            qA = fma2(sA, qA, ONEP); qB = fma2(sB, qB, ONEP);
            qC = fma2(sC, qC, ONEP); qD = fma2(sD, qD, ONEP);

            // exp(-1e6|u|) zone: min_k |v_k| = |w|*xmin[i] exactly; rare vote.
            if (__any_sync(0xffffffffu, fabsf(w) * xmv < TH_T)) {
                float v0,v1,v2,v3,v4,v5,v6,v7;
                float s0,s1,s2,s3,s4,s5,s6,s7;
                float n0,n1,n2,n3,n4,n5,n6,n7;
                float d0,d1,d2,d3,d4,d5,d6,d7;
                upk2(v0, v1, vA); upk2(v2, v3, vB);
                upk2(v4, v5, vC); upk2(v6, v7, vD);
                upk2(s0, s1, sA); upk2(s2, s3, sB);
                upk2(s4, s5, sC); upk2(s6, s7, sD);
                upk2(n0, n1, nmA); upk2(n2, n3, nmB);
                upk2(n4, n5, nmC); upk2(n6, n7, nmD);
                upk2(d0, d1, qA); upk2(d2, d3, qB);
                upk2(d4, d5, qC); upk2(d6, d7, qD);
                // num' = num + den*E, E = exp(-1e6|u|), u ~ v/2 (v==0 -> factor 1)
                if (s0 < TH2) n0 = fmaf(__expf(-5e5f*fabsf(v0)), d0, n0);
                if (s1 < TH2) n1 = fmaf(__expf(-5e5f*fabsf(v1)), d1, n1);
                if (s2 < TH2) n2 = fmaf(__expf(-5e5f*fabsf(v2)), d2, n2);
                if (s3 < TH2) n3 = fmaf(__expf(-5e5f*fabsf(v3)), d3, n3);
                if (s4 < TH2) n4 = fmaf(__expf(-5e5f*fabsf(v4)), d4, n4);
                if (s5 < TH2) n5 = fmaf(__expf(-5e5f*fabsf(v5)), d5, n5);
                if (s6 < TH2) n6 = fmaf(__expf(-5e5f*fabsf(v6)), d6, n6);
                if (s7 < TH2) n7 = fmaf(__expf(-5e5f*fabsf(v7)), d7, n7);
                nmA = pk2(n0, n1); nmB = pk2(n2, n3);
                nmC = pk2(n4, n5); nmD = pk2(n6, n7);
            }

            npA = mul2(npA, nmA); npB = mul2(npB, nmB);
            npC = mul2(npC, nmC); npD = mul2(npD, nmD);
            dpA = mul2(dpA, qA);  dpB = mul2(dpB, qB);
            dpC = mul2(dpC, qC);  dpD = mul2(dpD, qD);
        }
        float f0,f1,f2,f3,f4,f5,f6,f7, g0,g1,g2,g3,g4,g5,g6,g7;
        upk2(f0, f1, npA); upk2(f2, f3, npB);
        upk2(f4, f5, npC); upk2(f6, f7, npD);
        upk2(g0, g1, dpA); upk2(g2, g3, dpB);
        upk2(g4, g5, dpC); upk2(g6, g7, dpD);
        z[0] *= __fdividef(f0, g0); z[1] *= __fdividef(f1, g1);
        z[2] *= __fdividef(f2, g2); z[3] *= __fdividef(f3, g3);
        z[4] *= __fdividef(f4, g4); z[5] *= __fdividef(f5, g5);
        z[6] *= __fdividef(f6, g6); z[7] *= __fdividef(f7, g7);

        // Threshold early-exit: |z| is non-increasing (every |factor| <= ~1).
        // Once max|z| over the warp < ZCUT, the remaining >=16 factors push
        // both our z and the f32 reference's z to exact 0 -> set 0 and stop.
        float zm = fmaxf(fmaxf(fmaxf(fabsf(z[0]), fabsf(z[1])),
                               fmaxf(fabsf(z[2]), fabsf(z[3]))),
                         fmaxf(fmaxf(fabsf(z[4]), fabsf(z[5])),
                               fmaxf(fabsf(z[6]), fabsf(z[7]))));
        if (__all_sync(0xffffffffu, zm < ZCUT)) {
#pragma unroll
            for (int k = 0; k < BT; ++k) z[k] = 0.0f;
            break;
        }
    }

#pragma unroll
    for (int k = 0; k < BT; ++k) {
        float a = (1.0f + z[k]) + 1e-8f;
        float b = (1.0f - z[k]) + 1e-8f;
        out[(b0 + k) * NEURONS + n] = __logf(a / b);
    }
}

extern "C" void kernel_launch(void* const* d_in, const int* in_sizes, int n_in,
                              void* d_out, int out_size)
{
    const float* x = (const float*)d_in[0];   // [B, 128] float32
    const float* W = (const float*)d_in[1];   // [128, 512] float32
    float* out = (float*)d_out;               // [B, 512] float32

    const int B = in_sizes[0] / N_BITS;       // 2048
    dim3 grid(NEURONS / TPB, B / BT);         // (4, 256) -> 1024 blocks
    bp_input_layer_kernel<<<grid, TPB>>>(x, W, out);
}

// round 16
// speedup vs baseline: 3.8731x; 1.8486x over previous
#include <cuda_runtime.h>
#include <cuda_bf16.h>

#define N_BITS   128
#define NEURONS  512
#define BT       8      // batches per thread
#define TPB      128    // threads per block = neurons per block
#define CHUNK    16     // factors per partial product

typedef unsigned long long u64;

__device__ __forceinline__ u64 pk2(float lo, float hi) {
    u64 r; asm("mov.b64 %0, {%1, %2};" : "=l"(r) : "f"(lo), "f"(hi)); return r;
}
__device__ __forceinline__ void upk2(float& lo, float& hi, u64 p) {
    asm("mov.b64 {%0, %1}, %2;" : "=f"(lo), "=f"(hi) : "l"(p));
}
__device__ __forceinline__ u64 mul2(u64 a, u64 b) {
    u64 r; asm("mul.rn.f32x2 %0, %1, %2;" : "=l"(r) : "l"(a), "l"(b)); return r;
}
__device__ __forceinline__ u64 fma2(u64 a, u64 b, u64 c) {
    u64 r; asm("fma.rn.f32x2 %0, %1, %2, %3;" : "=l"(r) : "l"(a), "l"(b), "l"(c)); return r;
}

// [4/5] Pade for u = tanh(v/2), sigma = v^2:
//   num = v*(0.5 + A1*sigma + A2*sigma^2);  den = 1 + D1*sigma + D2*sigma^2
#define A1C  0.013888888888888888f
#define A2C  3.306878306878307e-5f
#define D1C  0.1111111111111111f
#define D2C  9.920634920634921e-4f
// exp(-1e6|u|) zone: E/|u| > 1e-4 only for |u| < ~2.1e-5 -> |v| < 4.2e-5.
#define TH_T 4.5e-5f
#define TH2  2.025e-9f               // TH_T^2
// Early-exit threshold. The f32 epilogue (1+z)+1e-8 rounds to exactly 1.0 for
// any |z| < eps/2 = 5.96e-8 (and +1e-8 is sub-eps), so |z| < ZCUT produces
// output bitwise 0.0 UNCONDITIONALLY - no remaining-factor argument needed.
// Reference z differs from ours by <~1.5% multiplicative -> also < 5.96e-8
// -> reference output is the same exact 0.0.  ZCUT = 2e-8 keeps 3x margin.
#define ZCUT 2e-8f

__global__ __launch_bounds__(TPB) void bp_input_layer_kernel(
    const float* __restrict__ x,      // [B, 128]
    const float* __restrict__ W,      // [128, 512]
    float* __restrict__ out)          // [B, 512]
{
    __shared__ __align__(16) float xs[N_BITS * BT];  // xs[i*8+k] = x[b0+k][i]
    __shared__ float xmin[N_BITS];                   // min_k |x[b0+k][i]|

    const int tid = threadIdx.x;
    const int n   = blockIdx.x * TPB + tid;          // neuron index
    const int b0  = blockIdx.y * BT;

    // Stage x (thread t owns bit-column t, coalesced across threads) + xmin
    {
        float mn = 1e30f;
#pragma unroll
        for (int k = 0; k < BT; ++k) {
            float v = x[(b0 + k) * N_BITS + tid];
            xs[tid * BT + k] = v;
            mn = fminf(mn, fabsf(v));
        }
        xmin[tid] = mn;
    }
    __syncthreads();

    const u64 ONEP = pk2(1.0f, 1.0f), HLFP = pk2(0.5f, 0.5f);
    const u64 A1P = pk2(A1C, A1C), A2P = pk2(A2C, A2C);
    const u64 D1P = pk2(D1C, D1C), D2P = pk2(D2C, D2C);

    float z[BT];
#pragma unroll
    for (int k = 0; k < BT; ++k) z[k] = 1.0f;

    const float* Wp = W + n;

    for (int c = 0; c < N_BITS / CHUNK; ++c) {
        u64 npA = ONEP, npB = ONEP, npC = ONEP, npD = ONEP;
        u64 dpA = ONEP, dpB = ONEP, dpC = ONEP, dpD = ONEP;
#pragma unroll
        for (int j = 0; j < CHUNK; ++j) {
            const int i = c * CHUNK + j;
            const float w   = Wp[i * NEURONS];           // coalesced LDG, L2-hot
            const float xmv = xmin[i];                   // LDS broadcast
            const u64 ww = pk2(w, w);
            const ulonglong2* xp = reinterpret_cast<const ulonglong2*>(&xs[i * BT]);
            const ulonglong2 q0 = xp[0], q1 = xp[1];     // 2x LDS.128 broadcast

            u64 vA = mul2(q0.x, ww), vB = mul2(q0.y, ww);
            u64 vC = mul2(q1.x, ww), vD = mul2(q1.y, ww);

            u64 sA = mul2(vA, vA), sB = mul2(vB, vB);    // sigma = v^2
            u64 sC = mul2(vC, vC), sD = mul2(vD, vD);

            // numerator: v * (0.5 + A1 s + A2 s^2)
            u64 pA = fma2(sA, A2P, A1P), pB = fma2(sB, A2P, A1P);
            u64 pC = fma2(sC, A2P, A1P), pD = fma2(sD, A2P, A1P);
            pA = fma2(sA, pA, HLFP); pB = fma2(sB, pB, HLFP);
            pC = fma2(sC, pC, HLFP); pD = fma2(sD, pD, HLFP);
            u64 nmA = mul2(vA, pA), nmB = mul2(vB, pB);
            u64 nmC = mul2(vC, pC), nmD = mul2(vD, pD);

            // denominator: 1 + D1 s + D2 s^2
            u64 qA = fma2(sA, D2P, D1P), qB = fma2(sB, D2P, D1P);
            u64 qC = fma2(sC, D2P, D1P), qD = fma2(sD, D2P, D1P);
            qA = fma2(sA, qA, ONEP); qB = fma2(sB, qB, ONEP);
            qC = fma2(sC, qC, ONEP); qD = fma2(sD, qD, ONEP);

            // exp(-1e6|u|) zone: min_k |v_k| = |w|*xmin[i] exactly; rare vote.
            if (__any_sync(0xffffffffu, fabsf(w) * xmv < TH_T)) {
                float v0,v1,v2,v3,v4,v5,v6,v7;
                float s0,s1,s2,s3,s4,s5,s6,s7;
                float n0,n1,n2,n3,n4,n5,n6,n7;
                float d0,d1,d2,d3,d4,d5,d6,d7;
                upk2(v0, v1, vA); upk2(v2, v3, vB);
                upk2(v4, v5, vC); upk2(v6, v7, vD);
                upk2(s0, s1, sA); upk2(s2, s3, sB);
                upk2(s4, s5, sC); upk2(s6, s7, sD);
                upk2(n0, n1, nmA); upk2(n2, n3, nmB);
                upk2(n4, n5, nmC); upk2(n6, n7, nmD);
                upk2(d0, d1, qA); upk2(d2, d3, qB);
                upk2(d4, d5, qC); upk2(d6, d7, qD);
                // num' = num + den*E, E = exp(-1e6|u|), u ~ v/2 (v==0 -> factor 1)
                if (s0 < TH2) n0 = fmaf(__expf(-5e5f*fabsf(v0)), d0, n0);
                if (s1 < TH2) n1 = fmaf(__expf(-5e5f*fabsf(v1)), d1, n1);
                if (s2 < TH2) n2 = fmaf(__expf(-5e5f*fabsf(v2)), d2, n2);
                if (s3 < TH2) n3 = fmaf(__expf(-5e5f*fabsf(v3)), d3, n3);
                if (s4 < TH2) n4 = fmaf(__expf(-5e5f*fabsf(v4)), d4, n4);
                if (s5 < TH2) n5 = fmaf(__expf(-5e5f*fabsf(v5)), d5, n5);
                if (s6 < TH2) n6 = fmaf(__expf(-5e5f*fabsf(v6)), d6, n6);
                if (s7 < TH2) n7 = fmaf(__expf(-5e5f*fabsf(v7)), d7, n7);
                nmA = pk2(n0, n1); nmB = pk2(n2, n3);
                nmC = pk2(n4, n5); nmD = pk2(n6, n7);
            }

            npA = mul2(npA, nmA); npB = mul2(npB, nmB);
            npC = mul2(npC, nmC); npD = mul2(npD, nmD);
            dpA = mul2(dpA, qA);  dpB = mul2(dpB, qB);
            dpC = mul2(dpC, qC);  dpD = mul2(dpD, qD);
        }
        float f0,f1,f2,f3,f4,f5,f6,f7, g0,g1,g2,g3,g4,g5,g6,g7;
        upk2(f0, f1, npA); upk2(f2, f3, npB);
        upk2(f4, f5, npC); upk2(f6, f7, npD);
        upk2(g0, g1, dpA); upk2(g2, g3, dpB);
        upk2(g4, g5, dpC); upk2(g6, g7, dpD);
        z[0] *= __fdividef(f0, g0); z[1] *= __fdividef(f1, g1);
        z[2] *= __fdividef(f2, g2); z[3] *= __fdividef(f3, g3);
        z[4] *= __fdividef(f4, g4); z[5] *= __fdividef(f5, g5);
        z[6] *= __fdividef(f6, g6); z[7] *= __fdividef(f7, g7);

        // Threshold early-exit: |z| is non-increasing (every |factor| <= ~1).
        // Any |z| < ZCUT already yields output bitwise 0.0 through the f32
        // epilogue, for us AND the reference -> set 0 and stop.
        float zm = fmaxf(fmaxf(fmaxf(fabsf(z[0]), fabsf(z[1])),
                               fmaxf(fabsf(z[2]), fabsf(z[3]))),
                         fmaxf(fmaxf(fabsf(z[4]), fabsf(z[5])),
                               fmaxf(fabsf(z[6]), fabsf(z[7]))));
        if (__all_sync(0xffffffffu, zm < ZCUT)) {
#pragma unroll
            for (int k = 0; k < BT; ++k) z[k] = 0.0f;
            break;
        }
    }

#pragma unroll
    for (int k = 0; k < BT; ++k) {
        float a = (1.0f + z[k]) + 1e-8f;
        float b = (1.0f - z[k]) + 1e-8f;
        out[(b0 + k) * NEURONS + n] = __logf(a / b);
    }
}

extern "C" void kernel_launch(void* const* d_in, const int* in_sizes, int n_in,
                              void* d_out, int out_size)
{
    const float* x = (const float*)d_in[0];   // [B, 128] float32
    const float* W = (const float*)d_in[1];   // [128, 512] float32
    float* out = (float*)d_out;               // [B, 512] float32

    const int B = in_sizes[0] / N_BITS;       // 2048
    dim3 grid(NEURONS / TPB, B / BT);         // (4, 256) -> 1024 blocks
    bp_input_layer_kernel<<<grid, TPB>>>(x, W, out);
}